// round 4
// baseline (speedup 1.0000x reference)
#include <cuda_runtime.h>
#include <math.h>

// ---------------- problem constants ----------------
#define BB    8
#define MM    1024
#define DM    768
#define HH    12
#define DHD   64
#define RR    32
#define RFF   384
#define DFF   3072
#define BMTOT (BB*MM)          // 8192
#define NCAT  (3*HH*RR)        // 1152

// ---------------- scratch (device globals; no allocs allowed) ----------------
__device__ float g_Pt  [DM   * NCAT];     // permuted P: [DM, 1152]
__device__ float g_T   [BMTOT* NCAT];     // x @ Pt
__device__ float g_Q   [BMTOT* DM];       // [B,H,M,DH]
__device__ float g_K   [BMTOT* DM];
__device__ float g_V   [BMTOT* DM];
__device__ float g_attn[BMTOT* DM];       // [B,M,H*DH]
__device__ float g_mid [BMTOT* RFF];      // rank-384 intermediates (reused)
__device__ float g_tmp [BMTOT* DM];
__device__ float g_x1  [BMTOT* DM];
__device__ float g_hdn [BMTOT* DFF];

// ---------------- helpers ----------------
__device__ __forceinline__ float gelu_exact(float v) {
    return 0.5f * v * (1.0f + erff(v * 0.70710678118654752440f));
}

// ---------------- P permute: [H,DM,R] x3 -> [DM, 3*H*R] ----------------
__global__ void permuteP_kernel(const float* __restrict__ Pq,
                                const float* __restrict__ Pk,
                                const float* __restrict__ Pv,
                                float* __restrict__ Pt) {
    int idx = blockIdx.x * 256 + threadIdx.x;
    if (idx >= DM * NCAT) return;
    int d = idx / NCAT;
    int n = idx - d * NCAT;
    int which = n / (HH*RR);
    int hn = n - which * (HH*RR);
    int h = hn >> 5;           // /32
    int r = hn & 31;
    const float* P = (which == 0) ? Pq : (which == 1) ? Pk : Pv;
    Pt[idx] = P[(h * DM + d) * RR + r];
}

// ---------------- generic tiled SGEMM: C[M,N] = A[M,K] @ B[K,N] (+bias)(+gelu) ----------------
// BM=BN=64, BK=16, 256 threads, 4x4 per-thread microtile. All dims divisible.
template<bool GELU>
__global__ __launch_bounds__(256)
void sgemm64_kernel(const float* __restrict__ A, const float* __restrict__ B,
                    const float* __restrict__ bias, float* __restrict__ C,
                    int Md, int Nd, int Kd) {
    __shared__ float As[16][68];   // padded (68%32=4) to soften transpose-store conflicts
    __shared__ float Bs[16][64];

    const int tid = threadIdx.x;
    const int tx = tid & 15;
    const int ty = tid >> 4;
    const int rowBase = blockIdx.y * 64;
    const int colBase = blockIdx.x * 64;

    const int ar = tid >> 2;            // 0..63
    const int ac = (tid & 3) << 2;      // 0,4,8,12
    const int br = tid >> 4;            // 0..15
    const int bc = (tid & 15) << 2;     // 0..60

    const float* Ap = A + (size_t)(rowBase + ar) * Kd + ac;
    const float* Bp = B + (size_t)br * Nd + colBase + bc;

    float acc[4][4];
    #pragma unroll
    for (int i = 0; i < 4; i++)
        #pragma unroll
        for (int j = 0; j < 4; j++) acc[i][j] = 0.0f;

    for (int k0 = 0; k0 < Kd; k0 += 16) {
        float4 av = *(const float4*)(Ap + k0);
        As[ac + 0][ar] = av.x;
        As[ac + 1][ar] = av.y;
        As[ac + 2][ar] = av.z;
        As[ac + 3][ar] = av.w;
        float4 bv = *(const float4*)(Bp + (size_t)k0 * Nd);
        *(float4*)&Bs[br][bc] = bv;
        __syncthreads();

        #pragma unroll
        for (int k = 0; k < 16; k++) {
            float4 a4 = *(const float4*)&As[k][ty << 2];
            float4 b4 = *(const float4*)&Bs[k][tx << 2];
            float avr[4] = {a4.x, a4.y, a4.z, a4.w};
            float bvr[4] = {b4.x, b4.y, b4.z, b4.w};
            #pragma unroll
            for (int i = 0; i < 4; i++)
                #pragma unroll
                for (int j = 0; j < 4; j++)
                    acc[i][j] += avr[i] * bvr[j];
        }
        __syncthreads();
    }

    const int col0 = colBase + (tx << 2);
    float b0 = 0.f, b1 = 0.f, b2 = 0.f, b3 = 0.f;
    if (bias) {
        b0 = bias[col0 + 0]; b1 = bias[col0 + 1];
        b2 = bias[col0 + 2]; b3 = bias[col0 + 3];
    }
    #pragma unroll
    for (int i = 0; i < 4; i++) {
        int row = rowBase + (ty << 2) + i;
        float4 o;
        o.x = acc[i][0] + b0;
        o.y = acc[i][1] + b1;
        o.z = acc[i][2] + b2;
        o.w = acc[i][3] + b3;
        if (GELU) {
            o.x = gelu_exact(o.x); o.y = gelu_exact(o.y);
            o.z = gelu_exact(o.z); o.w = gelu_exact(o.w);
        }
        *(float4*)(C + (size_t)row * Nd + col0) = o;
    }
}

// ---------------- QKV stage 2: Q/K/V[b,h,m,:] = T[bm, base+h*32+:] @ Vw[h] + bw[h] ----------------
__global__ __launch_bounds__(256)
void qkv2_kernel(const float* __restrict__ T,
                 const float* __restrict__ Vq, const float* __restrict__ Vk, const float* __restrict__ Vv,
                 const float* __restrict__ bq, const float* __restrict__ bk, const float* __restrict__ bv,
                 float* __restrict__ Q, float* __restrict__ K, float* __restrict__ V) {
    __shared__ float Ts[HH*RR];   // 384
    const int bm = blockIdx.x;
    const int which = blockIdx.y;
    const float* Vw = (which == 0) ? Vq : (which == 1) ? Vk : Vv;
    const float* bw = (which == 0) ? bq : (which == 1) ? bk : bv;
    float* O = (which == 0) ? Q : (which == 1) ? K : V;

    for (int i = threadIdx.x; i < HH*RR; i += 256)
        Ts[i] = T[(size_t)bm * NCAT + which * (HH*RR) + i];
    __syncthreads();

    const int b = bm / MM;
    const int m = bm - b * MM;
    for (int o = threadIdx.x; o < HH * DHD; o += 256) {
        int h = o >> 6;
        int d = o & 63;
        float acc = bw[h * DHD + d];
        const float* w = Vw + (size_t)h * (RR * DHD) + d;
        const float* ts = Ts + h * RR;
        #pragma unroll
        for (int r = 0; r < RR; r++)
            acc += ts[r] * w[r * DHD];
        O[(((size_t)b * HH + h) * MM + m) * DHD + d] = acc;
    }
}

// ---------------- flash attention: 1 thread = 1 query row ----------------
#define FA_BM 128
#define FA_BN 32
__global__ __launch_bounds__(FA_BM)
void flash_kernel(const float* __restrict__ Q, const float* __restrict__ K,
                  const float* __restrict__ V, const float* __restrict__ mask,
                  float* __restrict__ out) {
    __shared__ float Ks[FA_BN][DHD];
    __shared__ float Vs[FA_BN][DHD];
    __shared__ float Mk[FA_BN];

    const int bh = blockIdx.y;
    const int b  = bh / HH;
    const int h  = bh - b * HH;
    const int m  = blockIdx.x * FA_BM + threadIdx.x;

    const float* Qp = Q + ((size_t)bh * MM + m) * DHD;
    float q[DHD];
    #pragma unroll
    for (int d = 0; d < DHD; d += 4) {
        float4 v4 = *(const float4*)(Qp + d);
        q[d] = v4.x; q[d+1] = v4.y; q[d+2] = v4.z; q[d+3] = v4.w;
    }

    float o[DHD];
    #pragma unroll
    for (int d = 0; d < DHD; d++) o[d] = 0.0f;
    float mmax = -1e30f, lsum = 0.0f;

    for (int nb = 0; nb < MM / FA_BN; nb++) {
        const float* Kp = K + ((size_t)bh * MM + nb * FA_BN) * DHD;
        const float* Vp = V + ((size_t)bh * MM + nb * FA_BN) * DHD;
        for (int i = threadIdx.x; i < FA_BN * DHD / 4; i += FA_BM) {
            ((float4*)&Ks[0][0])[i] = ((const float4*)Kp)[i];
            ((float4*)&Vs[0][0])[i] = ((const float4*)Vp)[i];
        }
        if (threadIdx.x < FA_BN)
            Mk[threadIdx.x] = mask[(size_t)b * MM + nb * FA_BN + threadIdx.x];
        __syncthreads();

        float s[FA_BN];
        float bmax = -1e30f;
        #pragma unroll
        for (int j = 0; j < FA_BN; j++) {
            float a0 = 0.f, a1 = 0.f, a2 = 0.f, a3 = 0.f;
            #pragma unroll
            for (int d = 0; d < DHD; d += 4) {
                float4 kv = *(const float4*)&Ks[j][d];
                a0 += q[d]   * kv.x;
                a1 += q[d+1] * kv.y;
                a2 += q[d+2] * kv.z;
                a3 += q[d+3] * kv.w;
            }
            float sv = (a0 + a1 + a2 + a3) * 0.125f + Mk[j];
            s[j] = sv;
            bmax = fmaxf(bmax, sv);
        }
        float mnew = fmaxf(mmax, bmax);
        float corr = __expf(mmax - mnew);
        lsum *= corr;
        #pragma unroll
        for (int d = 0; d < DHD; d++) o[d] *= corr;
        #pragma unroll
        for (int j = 0; j < FA_BN; j++) {
            float p = __expf(s[j] - mnew);
            lsum += p;
            #pragma unroll
            for (int d = 0; d < DHD; d += 4) {
                float4 vv = *(const float4*)&Vs[j][d];
                o[d]   += p * vv.x;
                o[d+1] += p * vv.y;
                o[d+2] += p * vv.z;
                o[d+3] += p * vv.w;
            }
        }
        mmax = mnew;
        __syncthreads();
    }

    float inv = 1.0f / lsum;
    float* op = out + ((size_t)b * MM + m) * DM + h * DHD;
    #pragma unroll
    for (int d = 0; d < DHD; d += 4) {
        float4 v4;
        v4.x = o[d]   * inv;
        v4.y = o[d+1] * inv;
        v4.z = o[d+2] * inv;
        v4.w = o[d+3] * inv;
        *(float4*)(op + d) = v4;
    }
}

// ---------------- LayerNorm(xa + xb) * g + b, over 768 ----------------
__global__ __launch_bounds__(256)
void ln_kernel(const float* __restrict__ xa, const float* __restrict__ xb,
               const float* __restrict__ gw, const float* __restrict__ bw,
               float* __restrict__ out) {
    const int row = blockIdx.x;
    const int t = threadIdx.x;
    const float* pa = xa + (size_t)row * DM;
    const float* pb = xb + (size_t)row * DM;

    float v0 = pa[t]       + pb[t];
    float v1 = pa[t + 256] + pb[t + 256];
    float v2 = pa[t + 512] + pb[t + 512];

    float s  = v0 + v1 + v2;
    float ss = v0 * v0 + v1 * v1 + v2 * v2;
    #pragma unroll
    for (int off = 16; off > 0; off >>= 1) {
        s  += __shfl_xor_sync(0xffffffffu, s,  off);
        ss += __shfl_xor_sync(0xffffffffu, ss, off);
    }
    __shared__ float wsum[8], wsq[8], stats[2];
    int warp = t >> 5;
    if ((t & 31) == 0) { wsum[warp] = s; wsq[warp] = ss; }
    __syncthreads();
    if (t == 0) {
        float S = 0.f, SS = 0.f;
        #pragma unroll
        for (int w = 0; w < 8; w++) { S += wsum[w]; SS += wsq[w]; }
        float mu = S * (1.0f / DM);
        float var = SS * (1.0f / DM) - mu * mu;
        stats[0] = mu;
        stats[1] = rsqrtf(var + 1e-12f);
    }
    __syncthreads();
    float mu = stats[0], rstd = stats[1];
    float* po = out + (size_t)row * DM;
    po[t]       = (v0 - mu) * rstd * gw[t]       + bw[t];
    po[t + 256] = (v1 - mu) * rstd * gw[t + 256] + bw[t + 256];
    po[t + 512] = (v2 - mu) * rstd * gw[t + 512] + bw[t + 512];
}

// ---------------- launch ----------------
extern "C" void kernel_launch(void* const* d_in, const int* in_sizes, int n_in,
                              void* d_out, int out_size) {
    const float* x    = (const float*)d_in[0];
    const float* mask = (const float*)d_in[1];
    const float* Pq   = (const float*)d_in[2];
    const float* Vq   = (const float*)d_in[3];
    const float* bq   = (const float*)d_in[4];
    const float* Pk   = (const float*)d_in[5];
    const float* Vk   = (const float*)d_in[6];
    const float* bk   = (const float*)d_in[7];
    const float* Pv   = (const float*)d_in[8];
    const float* Vv   = (const float*)d_in[9];
    const float* bv   = (const float*)d_in[10];
    const float* Uo   = (const float*)d_in[11];
    const float* Vo   = (const float*)d_in[12];
    const float* bo   = (const float*)d_in[13];
    const float* U1   = (const float*)d_in[14];
    const float* V1   = (const float*)d_in[15];
    const float* b1   = (const float*)d_in[16];
    const float* U2   = (const float*)d_in[17];
    const float* V2   = (const float*)d_in[18];
    const float* b2   = (const float*)d_in[19];
    const float* ln1g = (const float*)d_in[20];
    const float* ln1b = (const float*)d_in[21];
    const float* ln2g = (const float*)d_in[22];
    const float* ln2b = (const float*)d_in[23];

    float *pPt, *pT, *pQ, *pK, *pV, *pA, *pMid, *pTmp, *pX1, *pH;
    cudaGetSymbolAddress((void**)&pPt,  g_Pt);
    cudaGetSymbolAddress((void**)&pT,   g_T);
    cudaGetSymbolAddress((void**)&pQ,   g_Q);
    cudaGetSymbolAddress((void**)&pK,   g_K);
    cudaGetSymbolAddress((void**)&pV,   g_V);
    cudaGetSymbolAddress((void**)&pA,   g_attn);
    cudaGetSymbolAddress((void**)&pMid, g_mid);
    cudaGetSymbolAddress((void**)&pTmp, g_tmp);
    cudaGetSymbolAddress((void**)&pX1,  g_x1);
    cudaGetSymbolAddress((void**)&pH,   g_hdn);

    // 1) permute P and stage-1 low-rank projection: T = x @ Pt  [8192, 1152]
    permuteP_kernel<<<(DM * NCAT + 255) / 256, 256>>>(Pq, Pk, Pv, pPt);
    sgemm64_kernel<false><<<dim3(NCAT / 64, BMTOT / 64), 256>>>(x, pPt, nullptr, pT, BMTOT, NCAT, DM);

    // 2) stage-2: Q/K/V = T @ V{q,k,v} + b  -> [B,H,M,DH]
    qkv2_kernel<<<dim3(BMTOT, 3), 256>>>(pT, Vq, Vk, Vv, bq, bk, bv, pQ, pK, pV);

    // 3) flash attention -> attn [B,M,H*DH]
    flash_kernel<<<dim3(MM / FA_BM, BB * HH), FA_BM>>>(pQ, pK, pV, mask, pA);

    // 4) Wo low-rank + bias, then LN1(x + .)
    sgemm64_kernel<false><<<dim3(RFF / 64, BMTOT / 64), 256>>>(pA, Uo, nullptr, pMid, BMTOT, RFF, DM);
    sgemm64_kernel<false><<<dim3(DM / 64, BMTOT / 64), 256>>>(pMid, Vo, bo, pTmp, BMTOT, DM, RFF);
    ln_kernel<<<BMTOT, 256>>>(x, pTmp, ln1g, ln1b, pX1);

    // 5) FFN: mid = x1@U1; hdn = gelu(mid@V1 + b1); mid = hdn@U2; y = mid@V2 + b2; LN2(x1 + y)
    sgemm64_kernel<false><<<dim3(RFF / 64, BMTOT / 64), 256>>>(pX1, U1, nullptr, pMid, BMTOT, RFF, DM);
    sgemm64_kernel<true ><<<dim3(DFF / 64, BMTOT / 64), 256>>>(pMid, V1, b1, pH, BMTOT, DFF, RFF);
    sgemm64_kernel<false><<<dim3(RFF / 64, BMTOT / 64), 256>>>(pH, U2, nullptr, pMid, BMTOT, RFF, DFF);
    sgemm64_kernel<false><<<dim3(DM / 64, BMTOT / 64), 256>>>(pMid, V2, b2, pTmp, BMTOT, DM, RFF);
    ln_kernel<<<BMTOT, 256>>>(pX1, pTmp, ln2g, ln2b, (float*)d_out);
}